// round 10
// baseline (speedup 1.0000x reference)
#include <cuda_runtime.h>
#include <cuda_fp16.h>
#include <cstdint>

// ============================================================================
// x[32,256,56,56] -> shift2d -> 1x1 conv W[256,256] -> BN -> ReLU
// GEMM: M = 100352, N = 256, K = 256. mma.sync m16n8k16 fp16/fp32.
// R9: N-split CTAs. CTA = 64 px x 128 cout x K=256 (full). B loaded once,
// A staged once, ONE barrier per CTA, barrier-free LDSM+MMA mainloop.
// 8 warps (2M x 4N, warp tile 32x32), 2 CTAs/SM.
// ============================================================================
#define CIN    256
#define COUT   256
#define HH     56
#define WWD    56
#define HWSZ   3136
#define NPIX   100352
#define CTA_M  64
#define NHALF  128
#define GRID   ((NPIX / CTA_M) * 2)   // 3136
#define NKK    16                     // K=256 in 16-k steps

// SMEM: A [64 rows][512B] at 0; B [128 rows][512B] at 32768. XOR-unit swizzle.
#define OFF_B      32768
#define SMEM_BYTES 98304

__device__ __half g_w[COUT * CIN];    // W[o][c] * inv[o], fp16, k-contiguous
__device__ float  g_bias[COUT];

#define DEVINL __device__ __forceinline__

DEVINL uint32_t smem_u32(const void* p) {
    uint32_t a;
    asm("{ .reg .u64 t; cvta.to.shared.u64 t, %1; cvt.u32.u64 %0, t; }"
        : "=r"(a) : "l"(p));
    return a;
}

#define CP_ASYNC16(dst_u32, src_ptr) \
    asm volatile("cp.async.cg.shared.global [%0], [%1], 16;" \
        :: "r"(dst_u32), "l"(src_ptr) : "memory")
#define CP_COMMIT() asm volatile("cp.async.commit_group;" ::: "memory")
#define CP_WAIT0()  asm volatile("cp.async.wait_group 0;"  ::: "memory")

#define MMA16816(d, a0, a1, a2, a3, b0, b1) \
    asm volatile("mma.sync.aligned.m16n8k16.row.col.f32.f16.f16.f32 " \
        "{%0,%1,%2,%3}, {%4,%5,%6,%7}, {%8,%9}, {%0,%1,%2,%3};" \
        : "+f"((d)[0]), "+f"((d)[1]), "+f"((d)[2]), "+f"((d)[3]) \
        : "r"(a0), "r"(a1), "r"(a2), "r"(a3), "r"(b0), "r"(b1))

#define LDSM4(r, addr) \
    asm volatile("ldmatrix.sync.aligned.m8n8.x4.shared.b16 {%0,%1,%2,%3}, [%4];" \
        : "=r"((r)[0]), "=r"((r)[1]), "=r"((r)[2]), "=r"((r)[3]) : "r"(addr))

#define STS128(addr, v) \
    asm volatile("st.shared.v4.b32 [%0], {%1,%2,%3,%4};" \
        :: "r"(addr), "r"((v).x), "r"((v).y), "r"((v).z), "r"((v).w) : "memory")

// channel -> shift direction (group starts 0,51,102,153,204)
DEVINL int ch_dir(int c) {
    return (c >= 204) ? 4 : (c >= 153) ? 3 : (c >= 102) ? 2 : (c >= 51) ? 1 : 0;
}

// ============================================================================
// prep: fold BN scale into W, fp16; compute bias.
// ============================================================================
__global__ void prep_kernel(const float* __restrict__ pw,
                            const float* __restrict__ gamma,
                            const float* __restrict__ beta,
                            const float* __restrict__ rmean,
                            const float* __restrict__ rvar)
{
    const int o  = blockIdx.x;
    const int c4 = threadIdx.x;            // 0..63
    const float inv_o = gamma[o] * rsqrtf(rvar[o] + 1e-5f);
    float4 v = *reinterpret_cast<const float4*>(pw + (size_t)o * CIN + c4 * 4);
    __half2 h01 = __floats2half2_rn(v.x * inv_o, v.y * inv_o);
    __half2 h23 = __floats2half2_rn(v.z * inv_o, v.w * inv_o);
    *reinterpret_cast<__half2*>(g_w + (size_t)o * CIN + c4 * 4)     = h01;
    *reinterpret_cast<__half2*>(g_w + (size_t)o * CIN + c4 * 4 + 2) = h23;
    if (o == 0) {
        #pragma unroll
        for (int j = 0; j < 4; ++j) {
            int c = c4 * 4 + j;
            float inv_c = gamma[c] * rsqrtf(rvar[c] + 1e-5f);
            g_bias[c] = beta[c] - rmean[c] * inv_c;
        }
    }
}

// ============================================================================
// main: 256 threads, 8 warps = 2(M) x 4(N), warp tile 32 x 32, K = 256 flat.
// ============================================================================
__global__ void __launch_bounds__(256, 2)
shiftconv_kernel(const float* __restrict__ x, float* __restrict__ out)
{
    extern __shared__ char smem[];

    const int tid  = threadIdx.x;
    const int warp = tid >> 5;
    const int lane = tid & 31;
    const int gr   = lane >> 2;
    const int lq   = lane & 3;

    const int tile = blockIdx.x >> 1;
    const int nh   = blockIdx.x & 1;       // N half: cout [nh*128, +128)

    const int warp_m  = (warp & 1) * 32;   // M offset within tile
    const int warp_nl = (warp >> 1) * 32;  // N offset within half

    const uint32_t sA_u32 = smem_u32(smem);
    const uint32_t sB_u32 = smem_u32(smem + OFF_B);

    // ---- B resident load (once per CTA): swizzled cp.async ------------------
    {
        const int r  = tid >> 1;             // row 0..127 (cout within half)
        const int uh = (tid & 1) * 16;       // unit half
        const __half* src = g_w + (size_t)(nh * NHALF + r) * CIN;
        #pragma unroll
        for (int j = 0; j < 16; ++j) {
            const int u = uh + j;            // 16B unit 0..31 (512B row)
            const uint32_t up = (uint32_t)u ^ (uint32_t)(r & 7);
            CP_ASYNC16(sB_u32 + (uint32_t)r * 512 + (up << 4), src + u * 8);
        }
        CP_COMMIT();
    }

    // ---- A staging (once per CTA): coalesced LDG f32 -> half2 -> STS.128 ----
    {
        const int pxl = tid & 63;
        const int c2  = tid >> 6;            // 0..3: channels [c2*64, +64)
        const int P   = tile * CTA_M + pxl;
        const int bb  = P / HWSZ;
        const int rr  = P - bb * HWSZ;
        const int hh  = rr / WWD;
        const int ww  = rr - hh * WWD;
        const float* xb = x + (size_t)bb * CIN * HWSZ;

        int  offs[5];
        bool vald[5];
        const int dxs[5] = {0, 1, -1, 0, 0};
        const int dys[5] = {0, 0, 0, 1, -1};
        #pragma unroll
        for (int d5 = 0; d5 < 5; ++d5) {
            int hs = hh - dys[d5], ws = ww - dxs[d5];
            vald[d5] = ((unsigned)hs < HH) && ((unsigned)ws < WWD);
            offs[d5] = hs * WWD + ws;
        }

        const uint32_t arow = sA_u32 + (uint32_t)pxl * 512;
        const uint32_t px7  = (uint32_t)(pxl & 7);
        #pragma unroll
        for (int g2 = 0; g2 < 4; ++g2) {     // 16 channels per sub-batch
            uint32_t hst[8];
            #pragma unroll
            for (int j = 0; j < 8; ++j) {
                const int ch0 = c2 * 64 + g2 * 16 + 2 * j;
                const int d0  = ch_dir(ch0);
                const int d1  = ch_dir(ch0 + 1);
                float v0 = vald[d0] ? __ldg(xb + (size_t)ch0       * HWSZ + offs[d0]) : 0.0f;
                float v1 = vald[d1] ? __ldg(xb + (size_t)(ch0 + 1) * HWSZ + offs[d1]) : 0.0f;
                __half2 h = __floats2half2_rn(v0, v1);
                hst[j] = *reinterpret_cast<uint32_t*>(&h);
            }
            const uint32_t u0 = (uint32_t)(c2 * 8 + g2 * 2);
            uint4 a0 = make_uint4(hst[0], hst[1], hst[2], hst[3]);
            uint4 a1 = make_uint4(hst[4], hst[5], hst[6], hst[7]);
            STS128(arow + ((u0       ^ px7) << 4), a0);
            STS128(arow + (((u0 + 1) ^ px7) << 4), a1);
        }
    }

    // ---- ldmatrix per-lane bases --------------------------------------------
    uint32_t a_base[2];
    const uint32_t a_c  = (uint32_t)(lane >> 4);
    const uint32_t a_x7 = (uint32_t)(lane & 7);
    {
        const int ar = lane & 15;
        #pragma unroll
        for (int mi = 0; mi < 2; ++mi)
            a_base[mi] = sA_u32 + (uint32_t)(warp_m + mi * 16 + ar) * 512;
    }
    uint32_t b_base[2];
    const int grp  = lane >> 3;
    const int nrow = lane - ((grp == 1 || grp == 2) ? 8 : (grp == 3) ? 16 : 0);
    const uint32_t b_c  = (uint32_t)(grp & 1);
    const uint32_t b_x7 = (uint32_t)(nrow & 7);
    #pragma unroll
    for (int f16 = 0; f16 < 2; ++f16)
        b_base[f16] = sB_u32 + (uint32_t)(warp_nl + f16 * 16 + nrow) * 512;

    float d[2][4][4];
    #pragma unroll
    for (int mi = 0; mi < 2; ++mi)
        #pragma unroll
        for (int f = 0; f < 4; ++f)
            #pragma unroll
            for (int e = 0; e < 4; ++e) d[mi][f][e] = 0.0f;

    // ---- the one barrier -----------------------------------------------------
    CP_WAIT0();
    __syncthreads();

    // ---- mainloop: pure LDSM + MMA, no syncs --------------------------------
    #pragma unroll
    for (int kk = 0; kk < NKK; ++kk) {
        uint32_t a[2][4], b[2][4];
        #pragma unroll
        for (int mi = 0; mi < 2; ++mi)
            LDSM4(a[mi], a_base[mi] + ((((uint32_t)(2 * kk) + a_c) ^ a_x7) << 4));
        #pragma unroll
        for (int f16 = 0; f16 < 2; ++f16)
            LDSM4(b[f16], b_base[f16] + ((((uint32_t)(2 * kk) + b_c) ^ b_x7) << 4));
        #pragma unroll
        for (int f16 = 0; f16 < 2; ++f16)
            #pragma unroll
            for (int mi = 0; mi < 2; ++mi) {
                MMA16816(d[mi][2*f16],     a[mi][0], a[mi][1], a[mi][2], a[mi][3],
                         b[f16][0], b[f16][1]);
                MMA16816(d[mi][2*f16 + 1], a[mi][0], a[mi][1], a[mi][2], a[mi][3],
                         b[f16][2], b[f16][3]);
            }
    }

    // ---- epilogue: bias + relu + store --------------------------------------
    #pragma unroll
    for (int mi = 0; mi < 2; ++mi) {
        #pragma unroll
        for (int h2 = 0; h2 < 2; ++h2) {
            const int pxe = warp_m + mi * 16 + gr + 8 * h2;
            const int Pe  = tile * CTA_M + pxe;
            const int be  = Pe / HWSZ;
            const int hwe = Pe - be * HWSZ;
            float* ob = out + (size_t)be * COUT * HWSZ + hwe;
            #pragma unroll
            for (int f = 0; f < 4; ++f) {
                const int o = nh * NHALF + warp_nl + f * 8 + lq * 2;
                const float2 bi = __ldg(reinterpret_cast<const float2*>(g_bias + o));
                float v0 = d[mi][f][h2 * 2 + 0] + bi.x;
                float v1 = d[mi][f][h2 * 2 + 1] + bi.y;
                ob[(size_t)o       * HWSZ] = fmaxf(v0, 0.0f);
                ob[(size_t)(o + 1) * HWSZ] = fmaxf(v1, 0.0f);
            }
        }
    }
}

// ============================================================================
extern "C" void kernel_launch(void* const* d_in, const int* in_sizes, int n_in,
                              void* d_out, int out_size) {
    const float* x     = (const float*)d_in[0];
    const float* pw    = (const float*)d_in[1];
    const float* gamma = (const float*)d_in[2];
    const float* beta  = (const float*)d_in[3];
    const float* rmean = (const float*)d_in[4];
    const float* rvar  = (const float*)d_in[5];
    float* out = (float*)d_out;

    static bool attr_set = false;
    if (!attr_set) {
        cudaFuncSetAttribute(shiftconv_kernel,
                             cudaFuncAttributeMaxDynamicSharedMemorySize, SMEM_BYTES);
        attr_set = true;
    }

    prep_kernel<<<COUT, 64>>>(pw, gamma, beta, rmean, rvar);
    shiftconv_kernel<<<GRID, 256, SMEM_BYTES>>>(x, out);
}

// round 11
// speedup vs baseline: 1.6821x; 1.6821x over previous
#include <cuda_runtime.h>
#include <cuda_fp16.h>
#include <cstdint>

// ============================================================================
// x[32,256,56,56] -> shift2d -> 1x1 conv W[256,256] -> BN -> ReLU
// GEMM: M = 100352, N = 256, K = 256. mma.sync m16n8k16 fp16/fp32.
// R10: small-CTA edition of R6. CTA = 64 px x 128 cout (N-half), 4 warps,
// warp tile 32x64, K chunked 64x4 with the R6 pipeline (split-half A stage).
// 4 CTAs/SM (regs 128, smem 48KB).
// ============================================================================
#define CIN    256
#define COUT   256
#define HH     56
#define WWD    56
#define HWSZ   3136
#define NPIX   100352
#define CTA_M  64
#define NHALF  128
#define GRID   ((NPIX / CTA_M) * 2)   // 3136
#define KCH    64
#define NCHUNK 4

// SMEM (bytes): A[buf][64 rows][128B] at 0 (2x8KB); B[buf][128 rows][128B]
// at 16384 (2x16KB). XOR-unit swizzled.
#define OFF_B      16384
#define A_BUF_BY   8192
#define B_BUF_BY   16384
#define SMEM_BYTES 49152

__device__ __half g_w[COUT * CIN];    // W[o][c] * inv[o], fp16, k-contiguous
__device__ float  g_bias[COUT];

#define DEVINL __device__ __forceinline__

DEVINL uint32_t smem_u32(const void* p) {
    uint32_t a;
    asm("{ .reg .u64 t; cvta.to.shared.u64 t, %1; cvt.u32.u64 %0, t; }"
        : "=r"(a) : "l"(p));
    return a;
}

#define CP_ASYNC16(dst_u32, src_ptr) \
    asm volatile("cp.async.cg.shared.global [%0], [%1], 16;" \
        :: "r"(dst_u32), "l"(src_ptr) : "memory")
#define CP_COMMIT() asm volatile("cp.async.commit_group;" ::: "memory")
#define CP_WAIT0()  asm volatile("cp.async.wait_group 0;"  ::: "memory")

#define MMA16816(d, a0, a1, a2, a3, b0, b1) \
    asm volatile("mma.sync.aligned.m16n8k16.row.col.f32.f16.f16.f32 " \
        "{%0,%1,%2,%3}, {%4,%5,%6,%7}, {%8,%9}, {%0,%1,%2,%3};" \
        : "+f"((d)[0]), "+f"((d)[1]), "+f"((d)[2]), "+f"((d)[3]) \
        : "r"(a0), "r"(a1), "r"(a2), "r"(a3), "r"(b0), "r"(b1))

#define LDSM4(r, addr) \
    asm volatile("ldmatrix.sync.aligned.m8n8.x4.shared.b16 {%0,%1,%2,%3}, [%4];" \
        : "=r"((r)[0]), "=r"((r)[1]), "=r"((r)[2]), "=r"((r)[3]) : "r"(addr))

#define STS128(addr, v) \
    asm volatile("st.shared.v4.b32 [%0], {%1,%2,%3,%4};" \
        :: "r"(addr), "r"((v).x), "r"((v).y), "r"((v).z), "r"((v).w) : "memory")

// channel -> shift direction (group starts 0,51,102,153,204)
DEVINL int ch_dir(int c) {
    return (c >= 204) ? 4 : (c >= 153) ? 3 : (c >= 102) ? 2 : (c >= 51) ? 1 : 0;
}

// ============================================================================
// prep: fold BN scale into W, fp16; compute bias.
// ============================================================================
__global__ void prep_kernel(const float* __restrict__ pw,
                            const float* __restrict__ gamma,
                            const float* __restrict__ beta,
                            const float* __restrict__ rmean,
                            const float* __restrict__ rvar)
{
    const int o  = blockIdx.x;
    const int c4 = threadIdx.x;            // 0..63
    const float inv_o = gamma[o] * rsqrtf(rvar[o] + 1e-5f);
    float4 v = *reinterpret_cast<const float4*>(pw + (size_t)o * CIN + c4 * 4);
    __half2 h01 = __floats2half2_rn(v.x * inv_o, v.y * inv_o);
    __half2 h23 = __floats2half2_rn(v.z * inv_o, v.w * inv_o);
    *reinterpret_cast<__half2*>(g_w + (size_t)o * CIN + c4 * 4)     = h01;
    *reinterpret_cast<__half2*>(g_w + (size_t)o * CIN + c4 * 4 + 2) = h23;
    if (o == 0) {
        #pragma unroll
        for (int j = 0; j < 4; ++j) {
            int c = c4 * 4 + j;
            float inv_c = gamma[c] * rsqrtf(rvar[c] + 1e-5f);
            g_bias[c] = beta[c] - rmean[c] * inv_c;
        }
    }
}

// ============================================================================
// main: 128 threads, 4 warps = 2(M) x 2(N), warp tile 32 x 64.
// ============================================================================
__global__ void __launch_bounds__(128, 4)
shiftconv_kernel(const float* __restrict__ x, float* __restrict__ out)
{
    extern __shared__ char smem[];

    const int tid  = threadIdx.x;
    const int warp = tid >> 5;
    const int lane = tid & 31;
    const int gr   = lane >> 2;
    const int lq   = lane & 3;

    const int tile = blockIdx.x >> 1;
    const int nh   = blockIdx.x & 1;        // cout half

    const int warp_m  = (warp & 1) * 32;    // M offset in tile
    const int warp_nl = (warp >> 1) * 64;   // N offset in half

    const uint32_t sA_u32 = smem_u32(smem);
    const uint32_t sB_u32 = smem_u32(smem + OFF_B);

    // ---- ldmatrix per-lane bases -------------------------------------------
    uint32_t a_base[2];
    const uint32_t a_c  = (uint32_t)(lane >> 4);
    const uint32_t a_x7 = (uint32_t)(lane & 7);
    {
        const int ar = lane & 15;
        #pragma unroll
        for (int mi = 0; mi < 2; ++mi)
            a_base[mi] = sA_u32 + (uint32_t)(warp_m + mi * 16 + ar) * 128;
    }
    uint32_t b_base[4];
    const int grp  = lane >> 3;
    const int nrow = lane - ((grp == 1 || grp == 2) ? 8 : (grp == 3) ? 16 : 0);
    const uint32_t b_c  = (uint32_t)(grp & 1);
    const uint32_t b_x7 = (uint32_t)(nrow & 7);
    #pragma unroll
    for (int f16 = 0; f16 < 4; ++f16)
        b_base[f16] = sB_u32 + (uint32_t)(warp_nl + f16 * 16 + nrow) * 128;

    // ---- A staging mapping: pixel + 16-ch slice within half-chunk -----------
    const int pxl = tid & 63;
    const int c2  = tid >> 6;              // 0..1
    const int P   = tile * CTA_M + pxl;
    const int bb  = P / HWSZ;
    const int rr  = P - bb * HWSZ;
    const int hh  = rr / WWD;
    const int ww  = rr - hh * WWD;
    const float* xb = x + (size_t)bb * CIN * HWSZ;

    int  offs[5];
    bool vald[5];
    {
        const int dxs[5] = {0, 1, -1, 0, 0};
        const int dys[5] = {0, 0, 0, 1, -1};
        #pragma unroll
        for (int d5 = 0; d5 < 5; ++d5) {
            int hs = hh - dys[d5], ws = ww - dxs[d5];
            vald[d5] = ((unsigned)hs < HH) && ((unsigned)ws < WWD);
            offs[d5] = hs * WWD + ws;
        }
    }
    const uint32_t a_row = sA_u32 + (uint32_t)pxl * 128;
    const uint32_t px7   = (uint32_t)(pxl & 7);

    // B staging mapping (128 rows x 8 units / 128 threads = 8 cp each)
    const int bu = tid & 7;
    const int bn = tid >> 3;               // 0..15
    const uint32_t b_st = sB_u32 + (uint32_t)bn * 128 +
                          (((uint32_t)bu ^ (uint32_t)(bn & 7)) << 4);

    uint32_t hstage[8];                    // 16 channels (one half-chunk slice)

    // half h of chunk: channels [chunk*64 + h*32 + c2*16, +16)
    auto ldg_half = [&](int chunk, int h) {
        const int c0 = chunk * KCH + h * 32 + c2 * 16;
        #pragma unroll
        for (int j = 0; j < 8; ++j) {
            const int ch0 = c0 + 2 * j;
            const int d0  = ch_dir(ch0);
            const int d1  = ch_dir(ch0 + 1);
            float v0 = vald[d0] ? __ldg(xb + (size_t)ch0       * HWSZ + offs[d0]) : 0.0f;
            float v1 = vald[d1] ? __ldg(xb + (size_t)(ch0 + 1) * HWSZ + offs[d1]) : 0.0f;
            __half2 hv = __floats2half2_rn(v0, v1);
            hstage[j] = *reinterpret_cast<uint32_t*>(&hv);
        }
    };

    auto sts_half = [&](int buf, int h) {
        const uint32_t u0 = (uint32_t)(h * 4 + c2 * 2);
        const uint32_t o  = (uint32_t)buf * A_BUF_BY;
        uint4 v0 = make_uint4(hstage[0], hstage[1], hstage[2], hstage[3]);
        uint4 v1 = make_uint4(hstage[4], hstage[5], hstage[6], hstage[7]);
        STS128(a_row + o + ((u0       ^ px7) << 4), v0);
        STS128(a_row + o + (((u0 + 1) ^ px7) << 4), v1);
    };

    auto cp_B = [&](int chunk, int buf) {
        const int c0 = chunk * KCH;
        #pragma unroll
        for (int itn = 0; itn < 8; ++itn) {
            const int n = bn + 16 * itn;
            const uint32_t dst = b_st + (uint32_t)(buf * 128 + 16 * itn) * 128;
            const __half* src = g_w + (size_t)(nh * NHALF + n) * CIN + c0 + bu * 8;
            CP_ASYNC16(dst, src);
        }
    };

    float d[2][8][4];
    #pragma unroll
    for (int mi = 0; mi < 2; ++mi)
        #pragma unroll
        for (int f = 0; f < 8; ++f)
            #pragma unroll
            for (int e = 0; e < 4; ++e) d[mi][f][e] = 0.0f;

    // compute half of a chunk: kk in {k0, k0+1}
    auto compute_half = [&](int buf, int k0) {
        const uint32_t aoff = (uint32_t)buf * A_BUF_BY;
        const uint32_t boff = (uint32_t)buf * B_BUF_BY;
        #pragma unroll
        for (int kx = 0; kx < 2; ++kx) {
            const uint32_t kk = (uint32_t)(k0 + kx);
            uint32_t a[2][4], b[4][4];
            #pragma unroll
            for (int mi = 0; mi < 2; ++mi)
                LDSM4(a[mi], a_base[mi] + aoff + (((2 * kk + a_c) ^ a_x7) << 4));
            #pragma unroll
            for (int f16 = 0; f16 < 4; ++f16)
                LDSM4(b[f16], b_base[f16] + boff + (((2 * kk + b_c) ^ b_x7) << 4));
            #pragma unroll
            for (int f16 = 0; f16 < 4; ++f16)
                #pragma unroll
                for (int mi = 0; mi < 2; ++mi) {
                    MMA16816(d[mi][2*f16],     a[mi][0], a[mi][1], a[mi][2], a[mi][3],
                             b[f16][0], b[f16][1]);
                    MMA16816(d[mi][2*f16 + 1], a[mi][0], a[mi][1], a[mi][2], a[mi][3],
                             b[f16][2], b[f16][3]);
                }
        }
    };

    // ---- prologue: chunk0 fully staged; half0 of chunk1 in hstage -----------
    cp_B(0, 0);
    CP_COMMIT();
    ldg_half(0, 0); sts_half(0, 0);
    ldg_half(0, 1); sts_half(0, 1);
    ldg_half(1, 0);

    // ---- main loop ----------------------------------------------------------
    #pragma unroll 1
    for (int i = 0; i < NCHUNK; ++i) {
        const int buf = i & 1;
        CP_WAIT0();
        __syncthreads();                    // A(i), B(i) visible

        if (i < NCHUNK - 1) {
            sts_half(buf ^ 1, 0);           // half0 of chunk i+1 (ldg'd earlier)
            ldg_half(i + 1, 1);             // half1 loads during kk 0-1
            cp_B(i + 1, buf ^ 1);
            CP_COMMIT();
        }

        compute_half(buf, 0);               // kk 0,1

        if (i < NCHUNK - 1) {
            sts_half(buf ^ 1, 1);           // half1 of chunk i+1
            if (i < NCHUNK - 2) ldg_half(i + 2, 0);   // half0 of chunk i+2
        }

        compute_half(buf, 2);               // kk 2,3
    }

    // ---- epilogue: bias + relu + store --------------------------------------
    #pragma unroll
    for (int mi = 0; mi < 2; ++mi) {
        #pragma unroll
        for (int h2 = 0; h2 < 2; ++h2) {
            const int pxe = warp_m + mi * 16 + gr + 8 * h2;
            const int Pe  = tile * CTA_M + pxe;
            const int be  = Pe / HWSZ;
            const int hwe = Pe - be * HWSZ;
            float* ob = out + (size_t)be * COUT * HWSZ + hwe;
            #pragma unroll
            for (int f = 0; f < 8; ++f) {
                const int o = nh * NHALF + warp_nl + f * 8 + lq * 2;
                const float2 bi = __ldg(reinterpret_cast<const float2*>(g_bias + o));
                float v0 = d[mi][f][h2 * 2 + 0] + bi.x;
                float v1 = d[mi][f][h2 * 2 + 1] + bi.y;
                ob[(size_t)o       * HWSZ] = fmaxf(v0, 0.0f);
                ob[(size_t)(o + 1) * HWSZ] = fmaxf(v1, 0.0f);
            }
        }
    }
}

// ============================================================================
extern "C" void kernel_launch(void* const* d_in, const int* in_sizes, int n_in,
                              void* d_out, int out_size) {
    const float* x     = (const float*)d_in[0];
    const float* pw    = (const float*)d_in[1];
    const float* gamma = (const float*)d_in[2];
    const float* beta  = (const float*)d_in[3];
    const float* rmean = (const float*)d_in[4];
    const float* rvar  = (const float*)d_in[5];
    float* out = (float*)d_out;

    static bool attr_set = false;
    if (!attr_set) {
        cudaFuncSetAttribute(shiftconv_kernel,
                             cudaFuncAttributeMaxDynamicSharedMemorySize, SMEM_BYTES);
        attr_set = true;
    }

    prep_kernel<<<COUT, 64>>>(pw, gamma, beta, rmean, rvar);
    shiftconv_kernel<<<GRID, 128, SMEM_BYTES>>>(x, out);
}

// round 13
// speedup vs baseline: 1.8823x; 1.1191x over previous
#include <cuda_runtime.h>
#include <cuda_fp16.h>
#include <cstdint>

// ============================================================================
// x[32,256,56,56] -> shift2d -> 1x1 conv W[256,256] -> BN -> ReLU
// GEMM: M = 100352, N = 256, K = 256. mma.sync m16n8k16 fp16/fp32.
// R11: two-pass. prep_x writes g_xt = fp16(shift2d(x)) in NHWC ([pixel][ch]);
// main GEMM stages BOTH operands via cp.async only (no LDG/pack/STS chain).
// Main: CTA = 64 px x 256 N, 8 warps (2Mx4N, tile 32x64), 2 CTAs/SM.
// ============================================================================
#define CIN    256
#define COUT   256
#define HH     56
#define WWD    56
#define HWSZ   3136
#define NPIX   100352
#define CTA_M  64
#define GRID   (NPIX / CTA_M)   // 1568
#define KCH    64
#define NCHUNK 4

// main SMEM: A[buf][64 rows][128B] at 0 (2x8KB); B[buf][256 rows][128B]
// at 16384 (2x32KB). XOR-unit swizzled.
#define OFF_B      16384
#define A_BUF_BY   8192
#define B_BUF_BY   32768
#define SMEM_BYTES 81920

// device-global scratch (sanctioned)
__device__ __align__(16) __half g_xt[NPIX * CIN];   // shifted x, NHWC fp16 (51MB)
__device__ __half g_w[COUT * CIN];                  // W * inv, fp16
__device__ float  g_bias[COUT];

#define DEVINL __device__ __forceinline__

DEVINL uint32_t smem_u32(const void* p) {
    uint32_t a;
    asm("{ .reg .u64 t; cvta.to.shared.u64 t, %1; cvt.u32.u64 %0, t; }"
        : "=r"(a) : "l"(p));
    return a;
}

#define CP_ASYNC16(dst_u32, src_ptr) \
    asm volatile("cp.async.cg.shared.global [%0], [%1], 16;" \
        :: "r"(dst_u32), "l"(src_ptr) : "memory")
#define CP_COMMIT() asm volatile("cp.async.commit_group;" ::: "memory")
#define CP_WAIT0()  asm volatile("cp.async.wait_group 0;"  ::: "memory")

#define MMA16816(d, a0, a1, a2, a3, b0, b1) \
    asm volatile("mma.sync.aligned.m16n8k16.row.col.f32.f16.f16.f32 " \
        "{%0,%1,%2,%3}, {%4,%5,%6,%7}, {%8,%9}, {%0,%1,%2,%3};" \
        : "+f"((d)[0]), "+f"((d)[1]), "+f"((d)[2]), "+f"((d)[3]) \
        : "r"(a0), "r"(a1), "r"(a2), "r"(a3), "r"(b0), "r"(b1))

#define LDSM4(r, addr) \
    asm volatile("ldmatrix.sync.aligned.m8n8.x4.shared.b16 {%0,%1,%2,%3}, [%4];" \
        : "=r"((r)[0]), "=r"((r)[1]), "=r"((r)[2]), "=r"((r)[3]) : "r"(addr))

// channel -> shift direction (group starts 0,51,102,153,204)
DEVINL int ch_dir(int c) {
    return (c >= 204) ? 4 : (c >= 153) ? 3 : (c >= 102) ? 2 : (c >= 51) ? 1 : 0;
}

// ============================================================================
// prep_w: fold BN scale into W, fp16; compute bias.
// ============================================================================
__global__ void prep_w_kernel(const float* __restrict__ pw,
                              const float* __restrict__ gamma,
                              const float* __restrict__ beta,
                              const float* __restrict__ rmean,
                              const float* __restrict__ rvar)
{
    const int o  = blockIdx.x;
    const int c4 = threadIdx.x;            // 0..63
    const float inv_o = gamma[o] * rsqrtf(rvar[o] + 1e-5f);
    float4 v = *reinterpret_cast<const float4*>(pw + (size_t)o * CIN + c4 * 4);
    __half2 h01 = __floats2half2_rn(v.x * inv_o, v.y * inv_o);
    __half2 h23 = __floats2half2_rn(v.z * inv_o, v.w * inv_o);
    *reinterpret_cast<__half2*>(g_w + (size_t)o * CIN + c4 * 4)     = h01;
    *reinterpret_cast<__half2*>(g_w + (size_t)o * CIN + c4 * 4 + 2) = h23;
    if (o == 0) {
        #pragma unroll
        for (int j = 0; j < 4; ++j) {
            int c = c4 * 4 + j;
            float inv_c = gamma[c] * rsqrtf(rvar[c] + 1e-5f);
            g_bias[c] = beta[c] - rmean[c] * inv_c;
        }
    }
}

// ============================================================================
// prep_x: g_xt[p][c] = fp16(shift2d(x)[b,c,h,w]); NCHW -> NHWC via SMEM tile.
// Block = 64 pixels x 64 channels; grid (1568, 4); 256 threads.
// ============================================================================
#define XPITCH 66   // fp16 per SMEM row (64 + 2 pad): 33-word pitch, odd
__global__ void __launch_bounds__(256)
prep_x_kernel(const float* __restrict__ x)
{
    __shared__ __half s[64 * XPITCH];

    const int pt  = blockIdx.x;        // pixel tile (64 px, never spans batch)
    const int cg  = blockIdx.y;        // channel group (64 ch)
    const int tid = threadIdx.x;

    // ---- load+shift+convert: thread = (pixel, 16-ch slice) ------------------
    const int px = tid & 63;
    const int P  = pt * 64 + px;
    const int bb = P / HWSZ;
    const int rr = P - bb * HWSZ;
    const int hh = rr / WWD;
    const int ww = rr - hh * WWD;
    const float* xb = x + (size_t)bb * CIN * HWSZ;

    int  offs[5];
    bool vald[5];
    {
        const int dxs[5] = {0, 1, -1, 0, 0};
        const int dys[5] = {0, 0, 0, 1, -1};
        #pragma unroll
        for (int d5 = 0; d5 < 5; ++d5) {
            int hs = hh - dys[d5], ws = ww - dxs[d5];
            vald[d5] = ((unsigned)hs < HH) && ((unsigned)ws < WWD);
            offs[d5] = hs * WWD + ws;
        }
    }

    const int cl0 = (tid >> 6) * 16;       // 16 channels per thread
    #pragma unroll
    for (int j = 0; j < 16; ++j) {
        const int cl = cl0 + j;
        const int c  = cg * 64 + cl;
        const int d5 = ch_dir(c);
        float v = vald[d5] ? __ldg(xb + (size_t)c * HWSZ + offs[d5]) : 0.0f;
        s[px * XPITCH + cl] = __float2half_rn(v);
    }
    __syncthreads();

    // ---- write NHWC: 2 x 16B units per thread -------------------------------
    #pragma unroll
    for (int t = 0; t < 2; ++t) {
        const int v   = tid * 2 + t;
        const int pxo = v >> 3;            // output pixel row
        const int u   = v & 7;             // 16B unit within 128B
        const uint32_t* sp = reinterpret_cast<const uint32_t*>(
            s + pxo * XPITCH + u * 8);
        uint4 val = make_uint4(sp[0], sp[1], sp[2], sp[3]);
        *reinterpret_cast<uint4*>(
            g_xt + (size_t)(pt * 64 + pxo) * CIN + cg * 64 + u * 8) = val;
    }
}

// ============================================================================
// main: 256 threads, 8 warps = 2(M) x 4(N), warp tile 32 x 64, all-cp.async.
// ============================================================================
__global__ void __launch_bounds__(256, 2)
shiftconv_kernel(float* __restrict__ out)
{
    extern __shared__ char smem[];

    const int tid  = threadIdx.x;
    const int warp = tid >> 5;
    const int lane = tid & 31;
    const int gr   = lane >> 2;
    const int lq   = lane & 3;

    const int warp_m = (warp & 1) * 32;    // M offset within CTA
    const int warp_n = (warp >> 1) * 64;   // N offset

    const uint32_t sA_u32 = smem_u32(smem);
    const uint32_t sB_u32 = smem_u32(smem + OFF_B);

    // ---- ldmatrix per-lane bases --------------------------------------------
    uint32_t a_base[2];
    const uint32_t a_c  = (uint32_t)(lane >> 4);
    const uint32_t a_x7 = (uint32_t)(lane & 7);
    {
        const int ar = lane & 15;
        #pragma unroll
        for (int mi = 0; mi < 2; ++mi)
            a_base[mi] = sA_u32 + (uint32_t)(warp_m + mi * 16 + ar) * 128;
    }
    uint32_t b_base[4];
    const int grp  = lane >> 3;
    const int nrow = lane - ((grp == 1 || grp == 2) ? 8 : (grp == 3) ? 16 : 0);
    const uint32_t b_c  = (uint32_t)(grp & 1);
    const uint32_t b_x7 = (uint32_t)(nrow & 7);
    #pragma unroll
    for (int f16 = 0; f16 < 4; ++f16)
        b_base[f16] = sB_u32 + (uint32_t)(warp_n + f16 * 16 + nrow) * 128;

    // ---- cp.async staging maps ----------------------------------------------
    // A: 64 rows x 8 units = 512 units, 2 per thread
    const int av0 = tid * 2;
    const int apx = av0 >> 3;              // pixel row (same for both units)
    const int au0 = av0 & 7;               // first unit (au0, au0+1; au0 even)
    const uint32_t a_dst0 = sA_u32 + (uint32_t)apx * 128 +
                            ((((uint32_t)au0)     ^ (uint32_t)(apx & 7)) << 4);
    const uint32_t a_dst1 = sA_u32 + (uint32_t)apx * 128 +
                            ((((uint32_t)au0 + 1) ^ (uint32_t)(apx & 7)) << 4);
    const __half* a_src = g_xt + (size_t)(blockIdx.x * CTA_M + apx) * CIN + au0 * 8;

    // B: 256 rows x 8 units / 256 thr = 8 each
    const int bu = tid & 7;
    const int bn = tid >> 3;
    const uint32_t b_st = sB_u32 + (uint32_t)bn * 128 +
                          (((uint32_t)bu ^ (uint32_t)(bn & 7)) << 4);

    auto cp_A = [&](int chunk, int buf) {
        const uint32_t o = (uint32_t)buf * A_BUF_BY;
        const __half* src = a_src + chunk * KCH;
        CP_ASYNC16(a_dst0 + o, src);
        CP_ASYNC16(a_dst1 + o, src + 8);
    };

    auto cp_B = [&](int chunk, int buf) {
        const int c0 = chunk * KCH;
        #pragma unroll
        for (int itn = 0; itn < 8; ++itn) {
            const int n = bn + 32 * itn;
            const uint32_t dst = b_st + (uint32_t)(buf * 256 + 32 * itn) * 128;
            const __half* src = g_w + (size_t)n * CIN + c0 + bu * 8;
            CP_ASYNC16(dst, src);
        }
    };

    float d[2][8][4];
    #pragma unroll
    for (int mi = 0; mi < 2; ++mi)
        #pragma unroll
        for (int f = 0; f < 8; ++f)
            #pragma unroll
            for (int e = 0; e < 4; ++e) d[mi][f][e] = 0.0f;

    // ---- prologue -----------------------------------------------------------
    cp_A(0, 0);
    cp_B(0, 0);
    CP_COMMIT();

    // ---- main loop: all-async staging ---------------------------------------
    #pragma unroll 1
    for (int i = 0; i < NCHUNK; ++i) {
        const int buf = i & 1;
        CP_WAIT0();
        __syncthreads();                    // A(i), B(i) visible

        if (i < NCHUNK - 1) {
            cp_A(i + 1, buf ^ 1);
            cp_B(i + 1, buf ^ 1);
            CP_COMMIT();                    // full compute block of slack
        }

        {
            const uint32_t aoff = (uint32_t)buf * A_BUF_BY;
            const uint32_t boff = (uint32_t)buf * B_BUF_BY;
            #pragma unroll
            for (int kk = 0; kk < 4; ++kk) {
                uint32_t a[2][4], b[4][4];
                #pragma unroll
                for (int mi = 0; mi < 2; ++mi)
                    LDSM4(a[mi], a_base[mi] + aoff +
                          ((((uint32_t)(2 * kk) + a_c) ^ a_x7) << 4));
                #pragma unroll
                for (int f16 = 0; f16 < 4; ++f16)
                    LDSM4(b[f16], b_base[f16] + boff +
                          ((((uint32_t)(2 * kk) + b_c) ^ b_x7) << 4));
                #pragma unroll
                for (int f16 = 0; f16 < 4; ++f16)
                    #pragma unroll
                    for (int mi = 0; mi < 2; ++mi) {
                        MMA16816(d[mi][2*f16],     a[mi][0], a[mi][1], a[mi][2], a[mi][3],
                                 b[f16][0], b[f16][1]);
                        MMA16816(d[mi][2*f16 + 1], a[mi][0], a[mi][1], a[mi][2], a[mi][3],
                                 b[f16][2], b[f16][3]);
                    }
            }
        }
    }

    // ---- epilogue: bias + relu + store --------------------------------------
    #pragma unroll
    for (int mi = 0; mi < 2; ++mi) {
        #pragma unroll
        for (int h2 = 0; h2 < 2; ++h2) {
            const int pxe = warp_m + mi * 16 + gr + 8 * h2;
            const int Pe  = blockIdx.x * CTA_M + pxe;
            const int be  = Pe / HWSZ;
            const int hwe = Pe - be * HWSZ;
            float* ob = out + (size_t)be * COUT * HWSZ + hwe;
            #pragma unroll
            for (int f = 0; f < 8; ++f) {
                const int o = warp_n + f * 8 + lq * 2;
                const float2 bi = __ldg(reinterpret_cast<const float2*>(g_bias + o));
                float v0 = d[mi][f][h2 * 2 + 0] + bi.x;
                float v1 = d[mi][f][h2 * 2 + 1] + bi.y;
                ob[(size_t)o       * HWSZ] = fmaxf(v0, 0.0f);
                ob[(size_t)(o + 1) * HWSZ] = fmaxf(v1, 0.0f);
            }
        }
    }
}

// ============================================================================
extern "C" void kernel_launch(void* const* d_in, const int* in_sizes, int n_in,
                              void* d_out, int out_size) {
    const float* x     = (const float*)d_in[0];
    const float* pw    = (const float*)d_in[1];
    const float* gamma = (const float*)d_in[2];
    const float* beta  = (const float*)d_in[3];
    const float* rmean = (const float*)d_in[4];
    const float* rvar  = (const float*)d_in[5];
    float* out = (float*)d_out;

    static bool attr_set = false;
    if (!attr_set) {
        cudaFuncSetAttribute(shiftconv_kernel,
                             cudaFuncAttributeMaxDynamicSharedMemorySize, SMEM_BYTES);
        attr_set = true;
    }

    prep_w_kernel<<<COUT, 64>>>(pw, gamma, beta, rmean, rvar);
    prep_x_kernel<<<dim3(GRID, 4), 256>>>(x);
    shiftconv_kernel<<<GRID, 256, SMEM_BYTES>>>(out);
}